// round 13
// baseline (speedup 1.0000x reference)
#include <cuda_runtime.h>

// Problem constants (fixed by reference)
#define NTIME 128
#define NBATCH 1024
#define NSAMP (NTIME*NBATCH)   // 131072
#define NSIZE 8
#define HID 64
#define IN_DIM 10
#define NC 12                  // 1 value col + 10 tangent cols + 1 zero pad
#define BS 32                  // samples per tile
#define NCOL (BS*NC)           // 384
#define NT 768                 // 8 row-groups x 96 col-chunks (32 samples x 3 parts)
#define NTILES (NSAMP / BS)    // 4096 (exact)
#define GRID 148

typedef unsigned long long u64;

struct SM {
  float A[HID*NCOL];        // 98304 B — single in-place state buffer
  float S8[NSIZE*NCOL];     // 12288 B — end-layer output
  float w1t[HID*HID];       // w_int[0] transposed: [k][i]
  float w2t[HID*HID];       // w_int[1] transposed
  float wedt[HID*2*NSIZE];  // w_end k-major + duplicated: [k][2r],[2r+1]
  float wsp[HID*16];        // w_start shifted+padded: [i][0]=0,[i][1..10]=row,[i][11..15]=0
  float bs[HID];
  float b1[HID];
  float b2[HID];
  float be[NSIZE];
  float pm[HID*BS];         // hidden-layer pre-activation exchange [row][sample]
  float pmS[HID*BS];        // start-layer pre-activation exchange [row][sample]
  float pconst, Econst;
};

__device__ __forceinline__ u64 pack2(float a, float b) {
  u64 r; asm("mov.b64 %0, {%1, %2};" : "=l"(r) : "f"(a), "f"(b)); return r;
}
__device__ __forceinline__ void unpack2(u64 v, float& a, float& b) {
  asm("mov.b64 {%0, %1}, %2;" : "=f"(a), "=f"(b) : "l"(v));
}
__device__ __forceinline__ void fma2(u64& d, u64 a, u64 b) {
  asm("fma.rn.f32x2 %0, %1, %2, %3;" : "=l"(d) : "l"(a), "l"(b), "l"(d));
}

// ---- Layer 1, VIRTUAL X: start-layer output reconstructed on the fly ----
// X[k][sample, col] = m_k * (col==0 ? pre_k : wsp[k][col]) with wsp padded so
// tangent col j reads wsp[k][j] and the pad col reads wsp[k][11]=0.
// Thread (ty,g): rows r0..r0+7, cols part*4..+3 of sample samp.
// Per k: 1 broadcast pmS read + 1 broadcast wsp float4 instead of a 4-wf X
// read. Math per output is the identical fma2 sequence -> exact numerics.
__device__ __forceinline__ void layer64_virt(const float* __restrict__ Wt,
                                             const float* __restrict__ bias,
                                             const float* __restrict__ pmS,
                                             const float* __restrict__ wsp,
                                             float* __restrict__ Y,
                                             float* __restrict__ pm,
                                             int r0, int g, int part, int samp)
{
  u64 acc[4][4];   // [col][rowpair]
  #pragma unroll
  for (int c = 0; c < 4; c++)
    #pragma unroll
    for (int rp = 0; rp < 4; rp++) acc[c][rp] = 0ull;
  if (part == 0) {
    #pragma unroll
    for (int rp = 0; rp < 4; rp++)
      acc[0][rp] = pack2(bias[r0 + 2*rp], bias[r0 + 2*rp + 1]);
  }

  const float* Wb = Wt + r0;

  #pragma unroll 4
  for (int k = 0; k < HID; k++) {
    float pre = pmS[k*BS + samp];
    float m = pre > 0.f ? 1.f : 0.f;
    float4 w4 = *reinterpret_cast<const float4*>(wsp + k*16 + part*4);
    float x0 = (part == 0) ? m*pre : m*w4.x;
    float x1 = m*w4.y, x2 = m*w4.z, x3 = m*w4.w;
    u64 xd[4];
    xd[0] = pack2(x0, x0); xd[1] = pack2(x1, x1);
    xd[2] = pack2(x2, x2); xd[3] = pack2(x3, x3);
    ulonglong2 wa = *reinterpret_cast<const ulonglong2*>(Wb + k*HID);
    ulonglong2 wb = *reinterpret_cast<const ulonglong2*>(Wb + k*HID + 4);
    u64 wp[4] = { wa.x, wa.y, wb.x, wb.y };
    #pragma unroll
    for (int c = 0; c < 4; c++)
      #pragma unroll
      for (int rp = 0; rp < 4; rp++)
        fma2(acc[c][rp], wp[rp], xd[c]);
  }

  if (part == 0) {
    #pragma unroll
    for (int rp = 0; rp < 4; rp++) {
      float p0, p1; unpack2(acc[0][rp], p0, p1);
      pm[(r0 + 2*rp)*BS + samp]     = p0;
      pm[(r0 + 2*rp + 1)*BS + samp] = p1;
    }
  }
  __syncthreads();   // pm visible (no X buffer to fence — X was virtual)

  float vv[4][8];
  #pragma unroll
  for (int c = 0; c < 4; c++)
    #pragma unroll
    for (int rp = 0; rp < 4; rp++)
      unpack2(acc[c][rp], vv[c][2*rp], vv[c][2*rp + 1]);

  #pragma unroll
  for (int r = 0; r < 8; r++) {
    float pre = pm[(r0 + r)*BS + samp];
    float m = pre > 0.f ? 1.f : 0.f;
    float4 o = make_float4(vv[0][r]*m, vv[1][r]*m, vv[2][r]*m, vv[3][r]*m);
    *reinterpret_cast<float4*>(Y + (r0 + r)*NCOL + g*4) = o;
  }
}

// ---- Layer 2: real X in smem, in place (unchanged from R12) ----
__device__ __forceinline__ void layer64_ip(const float* __restrict__ Wt,
                                           const float* __restrict__ bias,
                                           float* __restrict__ X,
                                           float* __restrict__ pm,
                                           int r0, int g, int part, int samp)
{
  u64 acc[4][4];   // [col][rowpair]
  #pragma unroll
  for (int c = 0; c < 4; c++)
    #pragma unroll
    for (int rp = 0; rp < 4; rp++) acc[c][rp] = 0ull;
  if (part == 0) {
    #pragma unroll
    for (int rp = 0; rp < 4; rp++)
      acc[0][rp] = pack2(bias[r0 + 2*rp], bias[r0 + 2*rp + 1]);
  }

  const float* Xb = X + g*4;
  const float* Wb = Wt + r0;

  #pragma unroll 4
  for (int k = 0; k < HID; k++) {
    float4 x = *reinterpret_cast<const float4*>(Xb + k*NCOL);
    u64 xd[4];
    xd[0] = pack2(x.x, x.x); xd[1] = pack2(x.y, x.y);
    xd[2] = pack2(x.z, x.z); xd[3] = pack2(x.w, x.w);
    ulonglong2 wa = *reinterpret_cast<const ulonglong2*>(Wb + k*HID);
    ulonglong2 wb = *reinterpret_cast<const ulonglong2*>(Wb + k*HID + 4);
    u64 wp[4] = { wa.x, wa.y, wb.x, wb.y };
    #pragma unroll
    for (int c = 0; c < 4; c++)
      #pragma unroll
      for (int rp = 0; rp < 4; rp++)
        fma2(acc[c][rp], wp[rp], xd[c]);
  }

  if (part == 0) {
    #pragma unroll
    for (int rp = 0; rp < 4; rp++) {
      float p0, p1; unpack2(acc[0][rp], p0, p1);
      pm[(r0 + 2*rp)*BS + samp]     = p0;
      pm[(r0 + 2*rp + 1)*BS + samp] = p1;
    }
  }
  __syncthreads();   // fences: all X reads done; pm visible

  float vv[4][8];
  #pragma unroll
  for (int c = 0; c < 4; c++)
    #pragma unroll
    for (int rp = 0; rp < 4; rp++)
      unpack2(acc[c][rp], vv[c][2*rp], vv[c][2*rp + 1]);

  #pragma unroll
  for (int r = 0; r < 8; r++) {
    float pre = pm[(r0 + r)*BS + samp];
    float m = pre > 0.f ? 1.f : 0.f;
    float4 o = make_float4(vv[0][r]*m, vv[1][r]*m, vv[2][r]*m, vv[3][r]*m);
    *reinterpret_cast<float4*>(X + (r0 + r)*NCOL + g*4) = o;
  }
}

__global__ __launch_bounds__(NT) void model_kernel(
    const float* __restrict__ y, const float* __restrict__ erate,
    const float* __restrict__ Tp, const float* __restrict__ Ep,
    const float* __restrict__ np_, const float* __restrict__ w_start,
    const float* __restrict__ b_start, const float* __restrict__ w_int,
    const float* __restrict__ b_int, const float* __restrict__ w_end,
    const float* __restrict__ b_end, float* __restrict__ out)
{
  extern __shared__ char smraw[];
  SM& s = *reinterpret_cast<SM*>(smraw);
  const int tid = threadIdx.x;

  // ---- one-time weight load ----
  for (int idx = tid; idx < HID*HID; idx += NT) {
    int i = idx / HID, k = idx % HID;
    s.w1t[k*HID + i] = w_int[idx];
    s.w2t[k*HID + i] = w_int[HID*HID + idx];
  }
  for (int idx = tid; idx < NSIZE*HID; idx += NT) {
    int r = idx / HID, k = idx % HID;
    float v = w_end[idx];
    s.wedt[k*2*NSIZE + 2*r]     = v;
    s.wedt[k*2*NSIZE + 2*r + 1] = v;
  }
  for (int idx = tid; idx < HID*16; idx += NT) {
    int i = idx >> 4, c = idx & 15;
    float v = 0.f;
    if (c >= 1 && c <= 10) v = w_start[i*IN_DIM + (c - 1)];
    s.wsp[idx] = v;
  }
  if (tid < HID) { s.bs[tid] = b_start[tid]; s.b1[tid] = b_int[tid]; s.b2[tid] = b_int[HID + tid]; }
  else if (tid < HID + NSIZE) s.be[tid - HID] = b_end[tid - HID];
  else if (tid == HID + NSIZE) { s.pconst = expf(np_[0]); s.Econst = expf(Ep[0]); }
  __syncthreads();   // fence weights/consts before any tile uses them

  // hidden-layer mapping: 96 threads per ty group -> 3 whole warps each
  const int ty   = tid / 96;      // 0..7 -> 8-row group
  const int g    = tid % 96;      // col chunk (4 floats)
  const int part = g % 3;         // 0 owns value col
  const int samp = g / 3;
  const int r0   = ty * 8;

  // start-phase mapping (threads 0..511: 16 row-groups x 32 samples)
  const int sty = tid / 32;       // 0..15 (for tid<512)
  const int stx = tid % 32;
  const int sr0 = sty * 4;

  // end-layer mapping: 192 col-pairs x 4 row-pairs
  const int epc = tid >> 2;       // col-pair 0..191
  const int erp = tid & 3;        // row-pair 0..3

  for (int tile = blockIdx.x; tile < NTILES; tile += GRID) {
    const int samp0 = tile * BS;

    // ---- start phase: compute pre-activations only -> pmS (coalesced) ----
    // pre_i = bs[i] + sum_j ws[i][j]*x[j], same fmaf order as before.
    if (tid < 512) {
      const int gg = samp0 + stx;
      float xin[IN_DIM];
      #pragma unroll
      for (int j = 0; j < NSIZE; j++) xin[j] = y[(size_t)gg*NSIZE + j];
      xin[8] = erate[gg];
      xin[9] = Tp[gg];
      #pragma unroll
      for (int r = 0; r < 4; r++) {
        int i = sr0 + r;
        const float4* wr4 = reinterpret_cast<const float4*>(s.wsp + i*16);
        float4 wa = wr4[0], wb = wr4[1], wc = wr4[2];
        float pre = s.bs[i];
        pre = fmaf(wa.y, xin[0], pre);
        pre = fmaf(wa.z, xin[1], pre);
        pre = fmaf(wa.w, xin[2], pre);
        pre = fmaf(wb.x, xin[3], pre);
        pre = fmaf(wb.y, xin[4], pre);
        pre = fmaf(wb.z, xin[5], pre);
        pre = fmaf(wb.w, xin[6], pre);
        pre = fmaf(wc.x, xin[7], pre);
        pre = fmaf(wc.y, xin[8], pre);
        pre = fmaf(wc.z, xin[9], pre);
        s.pmS[i*BS + stx] = pre;
      }
    }
    __syncthreads();                                    // bar 1

    // layer 1 with virtual X (reads pmS+wsp, writes A); bar 2 inside
    layer64_virt(s.w1t, s.b1, s.pmS, s.wsp, s.A, s.pm, r0, g, part, samp);
    __syncthreads();                                    // bar 3
    layer64_ip(s.w2t, s.b2, s.A, s.pm, r0, g, part, samp);   // bar 4 inside
    __syncthreads();                                    // bar 5

    // ---- end layer: S8[8 x NCOL] = We @ A (+b_end on value cols) ----
    {
      const int c = 2*epc;
      u64 acc0 = 0ull, acc1 = 0ull;
      const float* xb = s.A + c;
      const float* wt = s.wedt + 4*erp;
      #pragma unroll 8
      for (int k = 0; k < HID; k++) {
        u64 xv = *reinterpret_cast<const u64*>(xb + k*NCOL);
        ulonglong2 wv = *reinterpret_cast<const ulonglong2*>(wt + k*2*NSIZE);
        fma2(acc0, wv.x, xv);
        fma2(acc1, wv.y, xv);
      }
      int r = 2*erp;
      float lo0, hi0, lo1, hi1;
      unpack2(acc0, lo0, hi0);
      unpack2(acc1, lo1, hi1);
      if ((c % NC) == 0) { lo0 += s.be[r]; lo1 += s.be[r + 1]; }
      *reinterpret_cast<float2*>(s.S8 + r*NCOL + c)       = make_float2(lo0, hi0);
      *reinterpret_cast<float2*>(s.S8 + (r + 1)*NCOL + c) = make_float2(lo1, hi1);
    }
    __syncthreads();                                    // bar 6

    // ---- outputs: one thread per (sample, output row); scalars recomputed ----
    if (tid < BS*NSIZE) {
      int sm = tid >> 3;
      int r  = tid & 7;
      int gg = samp0 + sm;
      int cc = sm * NC;

      const float4* s4 = reinterpret_cast<const float4*>(s.S8 + r*NCOL + cc);
      float4 Sa = s4[0], Sb = s4[1], Sc = s4[2];
      float S[11] = { Sa.x, Sa.y, Sa.z, Sa.w, Sb.x, Sb.y, Sb.z, Sb.w,
                      Sc.x, Sc.y, Sc.z };

      float st0 = (sm == 0 && r == 0) ? S[0] : s.S8[cc];   // row-0 value col
      st0 = s.S8[cc];   // (uniform read; broadcast)
      float y0  = y[(size_t)gg*NSIZE];
      float sg  = (y0 > 0.f) ? 1.f : ((y0 < 0.f) ? -1.f : 0.f);
      float a   = fabsf(y0);
      float p   = s.pconst;
      float Ee  = s.Econst;
      float onep = 1.f + st0 * 1e-5f;
      float u   = a * onep;
      float gv  = (u > 0.f) ? powf(u, p) : 0.f;   // macaulay(g)=g since g>=0
      float dgdu = (u > 0.f) ? p * gv / u : 0.f;
      float coef = -Ee * sg * dgdu;
      float son  = sg * onep;
      float a5   = a * 1e-5f;

      float rate, j1[8], j2v, j3v;
      if (r == 0) {
        float er = erate[gg];
        rate = Ee * (er - gv * sg);
        #pragma unroll
        for (int j = 0; j < 8; j++) {
          float du = a5 * S[1 + j] + (j == 0 ? son : 0.f);
          j1[j] = coef * du;
        }
        j2v = Ee + coef * (a5 * S[9]);
        j3v = coef * (a5 * S[10]);
      } else {
        rate = S[0] * 1e-4f;
        #pragma unroll
        for (int j = 0; j < 8; j++) j1[j] = S[1 + j] * 1e-4f;
        j2v = S[9]  * 1e-4f;
        j3v = S[10] * 1e-4f;
      }

      out[(size_t)gg*NSIZE + r] = rate;
      const size_t b1o = (size_t)NSAMP * NSIZE;
      float* o1 = out + b1o + (size_t)gg*64 + (size_t)r*8;
      #pragma unroll
      for (int j = 0; j < 8; j++) o1[j] = j1[j];
      const size_t b2o = b1o + (size_t)NSAMP * 64;
      out[b2o + (size_t)gg*NSIZE + r] = j2v;
      out[b2o + (size_t)NSAMP*NSIZE + (size_t)gg*NSIZE + r] = j3v;
    }
    // no trailing barrier: next-tile pmS writes are ordered after bar 6 for
    // all threads; pmS's last readers (layer-1 k-loop) finished before bar 3;
    // S8 is next written only after next tile's bar 5.
  }
}

extern "C" void kernel_launch(void* const* d_in, const int* in_sizes, int n_in,
                              void* d_out, int out_size)
{
  const float* y       = (const float*)d_in[1];
  const float* erate   = (const float*)d_in[2];
  const float* T       = (const float*)d_in[3];
  const float* E       = (const float*)d_in[4];
  const float* n       = (const float*)d_in[5];
  const float* w_start = (const float*)d_in[6];
  const float* b_start = (const float*)d_in[7];
  const float* w_int   = (const float*)d_in[8];
  const float* b_int   = (const float*)d_in[9];
  const float* w_end   = (const float*)d_in[10];
  const float* b_end   = (const float*)d_in[11];
  float* out = (float*)d_out;

  int shbytes = (int)sizeof(SM);
  cudaFuncSetAttribute(model_kernel, cudaFuncAttributeMaxDynamicSharedMemorySize, shbytes);
  model_kernel<<<GRID, NT, shbytes>>>(y, erate, T, E, n, w_start, b_start,
                                      w_int, b_int, w_end, b_end, out);
}

// round 14
// speedup vs baseline: 1.1744x; 1.1744x over previous
#include <cuda_runtime.h>

// Problem constants (fixed by reference)
#define NTIME 128
#define NBATCH 1024
#define NSAMP (NTIME*NBATCH)   // 131072
#define NSIZE 8
#define HID 64
#define IN_DIM 10
#define NC 12                  // 1 value col + 10 tangent cols + 1 zero pad
#define BS 32                  // samples per tile
#define NCOL (BS*NC)           // 384
#define NT 768                 // 8 row-groups x 96 col-chunks (32 samples x 3 parts)
#define NTILES (NSAMP / BS)    // 4096 (exact)
#define GRID 148

typedef unsigned long long u64;

struct SM {
  float A[HID*NCOL];        // 98304 B — single in-place state buffer
  float S8[NSIZE*NCOL];     // 12288 B — end-layer output
  float w1t[HID*HID];       // w_int[0] transposed: [k][i]
  float w2t[HID*HID];       // w_int[1] transposed
  float wedt[HID*2*NSIZE];  // w_end k-major + duplicated: [k][2r],[2r+1]
  float ws[HID*IN_DIM];     // w_start row-major
  float bs[HID];
  float b1[HID];
  float b2[HID];
  float be[NSIZE];
  float pm[HID*BS];         // pre-activation exchange [row][sample]
  float pconst, Econst;
};

__device__ __forceinline__ u64 pack2(float a, float b) {
  u64 r; asm("mov.b64 %0, {%1, %2};" : "=l"(r) : "f"(a), "f"(b)); return r;
}
__device__ __forceinline__ void unpack2(u64 v, float& a, float& b) {
  asm("mov.b64 {%0, %1}, %2;" : "=f"(a), "=f"(b) : "l"(v));
}
__device__ __forceinline__ void fma2(u64& d, u64 a, u64 b) {
  asm("fma.rn.f32x2 %0, %1, %2, %3;" : "=l"(d) : "l"(a), "l"(b), "l"(d));
}

// Column-split hidden layer, IN PLACE on X (unchanged from R12 — exact).
__device__ __forceinline__ void layer64_ip(const float* __restrict__ Wt,
                                           const float* __restrict__ bias,
                                           float* __restrict__ X,
                                           float* __restrict__ pm,
                                           int r0, int g, int part, int samp)
{
  u64 acc[4][4];   // [col][rowpair]
  #pragma unroll
  for (int c = 0; c < 4; c++)
    #pragma unroll
    for (int rp = 0; rp < 4; rp++) acc[c][rp] = 0ull;
  if (part == 0) {
    #pragma unroll
    for (int rp = 0; rp < 4; rp++)
      acc[0][rp] = pack2(bias[r0 + 2*rp], bias[r0 + 2*rp + 1]);
  }

  const float* Xb = X + g*4;
  const float* Wb = Wt + r0;

  #pragma unroll 4
  for (int k = 0; k < HID; k++) {
    float4 x = *reinterpret_cast<const float4*>(Xb + k*NCOL);
    u64 xd[4];
    xd[0] = pack2(x.x, x.x); xd[1] = pack2(x.y, x.y);
    xd[2] = pack2(x.z, x.z); xd[3] = pack2(x.w, x.w);
    ulonglong2 wa = *reinterpret_cast<const ulonglong2*>(Wb + k*HID);
    ulonglong2 wb = *reinterpret_cast<const ulonglong2*>(Wb + k*HID + 4);
    u64 wp[4] = { wa.x, wa.y, wb.x, wb.y };
    #pragma unroll
    for (int c = 0; c < 4; c++)
      #pragma unroll
      for (int rp = 0; rp < 4; rp++)
        fma2(acc[c][rp], wp[rp], xd[c]);
  }

  if (part == 0) {
    #pragma unroll
    for (int rp = 0; rp < 4; rp++) {
      float p0, p1; unpack2(acc[0][rp], p0, p1);
      pm[(r0 + 2*rp)*BS + samp]     = p0;
      pm[(r0 + 2*rp + 1)*BS + samp] = p1;
    }
  }
  __syncthreads();   // fences: all X reads done; pm visible

  float vv[4][8];
  #pragma unroll
  for (int c = 0; c < 4; c++)
    #pragma unroll
    for (int rp = 0; rp < 4; rp++)
      unpack2(acc[c][rp], vv[c][2*rp], vv[c][2*rp + 1]);

  #pragma unroll
  for (int r = 0; r < 8; r++) {
    float pre = pm[(r0 + r)*BS + samp];
    float m = pre > 0.f ? 1.f : 0.f;
    // value col (part0,c0): m*pre == relu(pre); tangent cols: masked
    float4 o = make_float4(vv[0][r]*m, vv[1][r]*m, vv[2][r]*m, vv[3][r]*m);
    *reinterpret_cast<float4*>(X + (r0 + r)*NCOL + g*4) = o;
  }
}

__global__ __launch_bounds__(NT) void model_kernel(
    const float* __restrict__ y, const float* __restrict__ erate,
    const float* __restrict__ Tp, const float* __restrict__ Ep,
    const float* __restrict__ np_, const float* __restrict__ w_start,
    const float* __restrict__ b_start, const float* __restrict__ w_int,
    const float* __restrict__ b_int, const float* __restrict__ w_end,
    const float* __restrict__ b_end, float* __restrict__ out)
{
  extern __shared__ char smraw[];
  SM& s = *reinterpret_cast<SM*>(smraw);
  const int tid = threadIdx.x;

  // ---- one-time weight load: transpose hidden; w_end -> k-major duplicated ----
  for (int idx = tid; idx < HID*HID; idx += NT) {
    int i = idx / HID, k = idx % HID;
    s.w1t[k*HID + i] = w_int[idx];
    s.w2t[k*HID + i] = w_int[HID*HID + idx];
  }
  for (int idx = tid; idx < NSIZE*HID; idx += NT) {
    int r = idx / HID, k = idx % HID;
    float v = w_end[idx];
    s.wedt[k*2*NSIZE + 2*r]     = v;
    s.wedt[k*2*NSIZE + 2*r + 1] = v;
  }
  for (int idx = tid; idx < HID*IN_DIM; idx += NT) s.ws[idx] = w_start[idx];
  if (tid < HID) { s.bs[tid] = b_start[tid]; s.b1[tid] = b_int[tid]; s.b2[tid] = b_int[HID + tid]; }
  else if (tid < HID + NSIZE) s.be[tid - HID] = b_end[tid - HID];
  else if (tid == HID + NSIZE) { s.pconst = expf(np_[0]); s.Econst = expf(Ep[0]); }
  __syncthreads();   // fence weight/bias/const writes before any tile reads

  // hidden-layer mapping: 96 threads per ty group -> 3 whole warps each
  const int ty   = tid / 96;      // 0..7 -> 8-row group
  const int g    = tid % 96;      // col chunk (4 floats)
  const int part = g % 3;         // 0 owns value col
  const int samp = g / 3;
  const int r0   = ty * 8;

  // start-layer mapping (threads 0..511: 16 row-groups x 32 samples)
  const int sty = tid / 32;       // 0..15 (for tid<512)
  const int stx = tid % 32;
  const int sr0 = sty * 4;
  const int sc0 = stx * NC;

  for (int tile = blockIdx.x; tile < NTILES; tile += GRID) {
    const int samp0 = tile * BS;

    // ---- start layer straight from GLOBAL inputs (threads 0..511) ----
    // col0 = relu(Ws x + b); tangent col j = mask*Ws[:,j]; pad=0
    if (tid < 512) {
      const int gg = samp0 + stx;
      float xin[IN_DIM];
      #pragma unroll
      for (int j = 0; j < NSIZE; j++) xin[j] = y[(size_t)gg*NSIZE + j];
      xin[8] = erate[gg];
      xin[9] = Tp[gg];
      #pragma unroll
      for (int r = 0; r < 4; r++) {
        int i = sr0 + r;
        float wrow[IN_DIM];
        #pragma unroll
        for (int j = 0; j < IN_DIM; j++) wrow[j] = s.ws[i*IN_DIM + j];
        float pre = s.bs[i];
        #pragma unroll
        for (int j = 0; j < IN_DIM; j++) pre = fmaf(wrow[j], xin[j], pre);
        float m = pre > 0.f ? 1.f : 0.f;
        float v0 = pre > 0.f ? pre : 0.f;
        float4* ar = reinterpret_cast<float4*>(s.A + i*NCOL + sc0);
        ar[0] = make_float4(v0, m*wrow[0], m*wrow[1], m*wrow[2]);
        ar[1] = make_float4(m*wrow[3], m*wrow[4], m*wrow[5], m*wrow[6]);
        ar[2] = make_float4(m*wrow[7], m*wrow[8], m*wrow[9], 0.f);
      }
    }
    __syncthreads();                                    // bar 1

    layer64_ip(s.w1t, s.b1, s.A, s.pm, r0, g, part, samp);   // bar 2 inside
    __syncthreads();                                    // bar 3
    layer64_ip(s.w2t, s.b2, s.A, s.pm, r0, g, part, samp);   // bar 4 inside
    __syncthreads();                                    // bar 5

    // ---- end layer on threads 0..383: rows as quads (R=4), col-pairs ----
    // Lane pairs share the X pair load (broadcast-pair -> 1 wf); W is two
    // broadcast LDS.128 from duplicated wedt. k strictly sequential 0..63
    // per output, bias after the loop (exact numerics).
    if (tid < 384) {
      const int ecp = tid >> 1;       // col-pair 0..191
      const int erq = tid & 1;        // row-quad 0..1
      const int c = 2*ecp;
      u64 acc0 = 0ull, acc1 = 0ull, acc2 = 0ull, acc3 = 0ull;
      const float* xb = s.A + c;
      const float* wt = s.wedt + 8*erq;
      #pragma unroll 8
      for (int k = 0; k < HID; k++) {
        u64 xv = *reinterpret_cast<const u64*>(xb + k*NCOL);
        ulonglong2 w01 = *reinterpret_cast<const ulonglong2*>(wt + k*2*NSIZE);
        ulonglong2 w23 = *reinterpret_cast<const ulonglong2*>(wt + k*2*NSIZE + 4);
        fma2(acc0, w01.x, xv);
        fma2(acc1, w01.y, xv);
        fma2(acc2, w23.x, xv);
        fma2(acc3, w23.y, xv);
      }
      const int rb = 4*erq;
      float lo, hi;
      unpack2(acc0, lo, hi);
      if ((c % NC) == 0) lo += s.be[rb];
      *reinterpret_cast<float2*>(s.S8 + (rb    )*NCOL + c) = make_float2(lo, hi);
      unpack2(acc1, lo, hi);
      if ((c % NC) == 0) lo += s.be[rb + 1];
      *reinterpret_cast<float2*>(s.S8 + (rb + 1)*NCOL + c) = make_float2(lo, hi);
      unpack2(acc2, lo, hi);
      if ((c % NC) == 0) lo += s.be[rb + 2];
      *reinterpret_cast<float2*>(s.S8 + (rb + 2)*NCOL + c) = make_float2(lo, hi);
      unpack2(acc3, lo, hi);
      if ((c % NC) == 0) lo += s.be[rb + 3];
      *reinterpret_cast<float2*>(s.S8 + (rb + 3)*NCOL + c) = make_float2(lo, hi);
    }
    __syncthreads();                                    // bar 6

    // ---- outputs on threads 512..767: overlap with next tile's start layer
    // (threads 0..511 proceed directly to the next start phase after bar 6).
    // Safety: S8 reads finish before these threads join bar 1 of tile t+1,
    // and S8 is next written only after bar 5 of t+1.
    if (tid >= 512) {
      int otid = tid - 512;
      int sm = otid >> 3;
      int r  = otid & 7;
      int gg = samp0 + sm;
      int cc = sm * NC;

      const float4* s4 = reinterpret_cast<const float4*>(s.S8 + r*NCOL + cc);
      float4 Sa = s4[0], Sb = s4[1], Sc = s4[2];
      float S[11] = { Sa.x, Sa.y, Sa.z, Sa.w, Sb.x, Sb.y, Sb.z, Sb.w,
                      Sc.x, Sc.y, Sc.z };

      float st0 = s.S8[cc];               // row-0 value col (broadcast)
      float y0  = y[(size_t)gg*NSIZE];
      float sg  = (y0 > 0.f) ? 1.f : ((y0 < 0.f) ? -1.f : 0.f);
      float a   = fabsf(y0);
      float p   = s.pconst;
      float Ee  = s.Econst;
      float onep = 1.f + st0 * 1e-5f;
      float u   = a * onep;
      float gv  = (u > 0.f) ? powf(u, p) : 0.f;   // macaulay(g)=g since g>=0
      float dgdu = (u > 0.f) ? p * gv / u : 0.f;
      float coef = -Ee * sg * dgdu;
      float son  = sg * onep;
      float a5   = a * 1e-5f;

      float rate, j1[8], j2v, j3v;
      if (r == 0) {
        float er = erate[gg];
        rate = Ee * (er - gv * sg);
        #pragma unroll
        for (int j = 0; j < 8; j++) {
          float du = a5 * S[1 + j] + (j == 0 ? son : 0.f);
          j1[j] = coef * du;
        }
        j2v = Ee + coef * (a5 * S[9]);
        j3v = coef * (a5 * S[10]);
      } else {
        rate = S[0] * 1e-4f;
        #pragma unroll
        for (int j = 0; j < 8; j++) j1[j] = S[1 + j] * 1e-4f;
        j2v = S[9]  * 1e-4f;
        j3v = S[10] * 1e-4f;
      }

      out[(size_t)gg*NSIZE + r] = rate;
      const size_t b1o = (size_t)NSAMP * NSIZE;
      float* o1 = out + b1o + (size_t)gg*64 + (size_t)r*8;
      #pragma unroll
      for (int j = 0; j < 8; j++) o1[j] = j1[j];
      const size_t b2o = b1o + (size_t)NSAMP * 64;
      out[b2o + (size_t)gg*NSIZE + r] = j2v;
      out[b2o + (size_t)NSAMP*NSIZE + (size_t)gg*NSIZE + r] = j3v;
    }
    // no trailing barrier (see safety note above; A-write vs end-layer-read
    // is fenced by bar 6).
  }
}

extern "C" void kernel_launch(void* const* d_in, const int* in_sizes, int n_in,
                              void* d_out, int out_size)
{
  const float* y       = (const float*)d_in[1];
  const float* erate   = (const float*)d_in[2];
  const float* T       = (const float*)d_in[3];
  const float* E       = (const float*)d_in[4];
  const float* n       = (const float*)d_in[5];
  const float* w_start = (const float*)d_in[6];
  const float* b_start = (const float*)d_in[7];
  const float* w_int   = (const float*)d_in[8];
  const float* b_int   = (const float*)d_in[9];
  const float* w_end   = (const float*)d_in[10];
  const float* b_end   = (const float*)d_in[11];
  float* out = (float*)d_out;

  int shbytes = (int)sizeof(SM);
  cudaFuncSetAttribute(model_kernel, cudaFuncAttributeMaxDynamicSharedMemorySize, shbytes);
  model_kernel<<<GRID, NT, shbytes>>>(y, erate, T, E, n, w_start, b_start,
                                      w_int, b_int, w_end, b_end, out);
}